// round 15
// baseline (speedup 1.0000x reference)
#include <cuda_runtime.h>
#include <cstdint>

#define D_IN   2048
#define F_MID  1024
#define NEXP   32
#define CAP    512
#define TTOK   8192

#define SA   20u    // A smem row stride (words)
#define SBW  136u   // B smem row stride (words)
#define NSTF 4      // stages, fused kernel
#define NST2 3      // stages, gemm2 (single-barrier-safe; 56.8KB -> 2 CTA/SM)

// per-stage words
#define SFW  (128u * SA + 2u * 16u * SBW)    // fused: 2560 + 4352 = 6912
#define S2W  (128u * SA + 16u * SBW)         // gemm2: 2560 + 2176 = 4736
#define SMEMF (NSTF * SFW * 4u)              // 110592 B
#define SMEM2 (NST2 * S2W * 4u)              // 56832 B

// scratch (__device__ globals: allocation-free rule)
__device__ int   g_slots[NEXP * CAP];
__device__ int   g_counts[NEXP];
__device__ float g_H[(size_t)NEXP * CAP * F_MID];  // 64 MB

__device__ __forceinline__ uint32_t smem_u32(const void* p) {
    uint32_t a;
    asm("{ .reg .u64 t; cvta.to.shared.u64 t, %1; cvt.u32.u64 %0, t; }" : "=r"(a) : "l"(p));
    return a;
}
__device__ __forceinline__ uint32_t f2tf(float f) {
    uint32_t u; asm("cvt.rna.tf32.f32 %0, %1;" : "=r"(u) : "f"(f)); return u;
}
__device__ __forceinline__ uint32_t c2t(uint32_t raw) {
    return f2tf(__uint_as_float(raw));
}
__device__ __forceinline__ void cpa16(uint32_t dst, const float* src) {
    asm volatile("cp.async.cg.shared.global [%0], [%1], 16;" :: "r"(dst), "l"(src) : "memory");
}
__device__ __forceinline__ void cpa_commit() {
    asm volatile("cp.async.commit_group;" ::: "memory");
}
template<int N> __device__ __forceinline__ void cpa_wait() {
    asm volatile("cp.async.wait_group %0;" :: "n"(N) : "memory");
}
__device__ __forceinline__ void mma8(float* c, const uint32_t* a, const uint32_t* b) {
    asm volatile(
        "mma.sync.aligned.m16n8k8.row.col.f32.tf32.tf32.f32 "
        "{%0,%1,%2,%3}, {%4,%5,%6,%7}, {%8,%9}, {%0,%1,%2,%3};"
        : "+f"(c[0]), "+f"(c[1]), "+f"(c[2]), "+f"(c[3])
        : "r"(a[0]), "r"(a[1]), "r"(a[2]), "r"(a[3]), "r"(b[0]), "r"(b[1]));
}

// ---------------------------------------------------------------- dispatch
__global__ void build_slots(const int* __restrict__ idx) {
    const int e = blockIdx.x, tid = threadIdx.x;
    const int lane = tid & 31, w = tid >> 5;
    __shared__ int wsum[8];
    int base = 0;
    for (int start = 0; start < TTOK; start += 256) {
        int t = start + tid;
        bool m = (idx[t] == e);
        unsigned bal = __ballot_sync(0xffffffffu, m);
        if (lane == 0) wsum[w] = __popc(bal);
        __syncthreads();
        int woff = 0, tot = 0;
        #pragma unroll
        for (int i = 0; i < 8; i++) { int v = wsum[i]; tot += v; if (i < w) woff += v; }
        if (m) {
            int pos = base + woff + __popc(bal & ((1u << lane) - 1u));
            if (pos < CAP) g_slots[e * CAP + pos] = t;
        }
        base += tot;
        __syncthreads();
    }
    if (tid == 0) g_counts[e] = base < CAP ? base : CAP;
}

// ---------------------------------------------------------------- fused GEMM1+3
// g_H = silu(gatherX @ W1 + b1) * (gatherX @ W3 + b3)
// R13 structure (best passing): 4-stage cp.async, single barrier/chunk,
// exact tail waits, ks-fragment double-buffer. Grid: (n-tiles, m-tiles, e).
__global__ __launch_bounds__(256, 1) void gemm13_f(
    const float* __restrict__ x,
    const float* __restrict__ W1, const float* __restrict__ b1,
    const float* __restrict__ W3, const float* __restrict__ b3)
{
    constexpr int NK = D_IN / 16;   // 128

    const int e  = blockIdx.z;
    const int m0 = blockIdx.y * 128;
    const int n0 = blockIdx.x * 128;
    const int count = g_counts[e];
    if (m0 >= count) return;

    extern __shared__ uint32_t sm[];
    const uint32_t sbase = smem_u32(sm);

    const int tid = threadIdx.x, wid = tid >> 5, lane = tid & 31;
    const int wm = wid >> 2, wn = wid & 3;
    const int qg = lane >> 2, qt = lane & 3;

    const int ar  = tid >> 2;
    const int ak4 = (tid & 3) * 4;
    const float* ap[2];
    uint32_t a_st[2];
    #pragma unroll
    for (int j = 0; j < 2; j++) {
        const int grow = m0 + ar + 64 * j;
        const int tok = (grow < count) ? g_slots[e * CAP + grow] : 0;
        ap[j]   = x + (size_t)tok * D_IN + ak4;
        a_st[j] = (uint32_t)(ar + 64 * j) * SA + ak4;
    }
    const int bkr = tid >> 5;
    const int bn4 = (tid & 31) * 4;
    const float* w1p = W1 + ((size_t)e * D_IN + bkr) * F_MID + n0 + bn4;
    const float* w3p = W3 + ((size_t)e * D_IN + bkr) * F_MID + n0 + bn4;
    const uint32_t b_st[2] = { (uint32_t)bkr * SBW + bn4, (uint32_t)(bkr + 8) * SBW + bn4 };

    auto issue = [&](int kt) {
        const uint32_t so = (uint32_t)(kt & (NSTF - 1)) * SFW;
        #pragma unroll
        for (int j = 0; j < 2; j++)
            cpa16(sbase + (so + a_st[j]) * 4, ap[j] + kt * 16);
        #pragma unroll
        for (int j = 0; j < 2; j++) {
            const size_t ko = ((size_t)kt * 16 + 8 * j) * F_MID;
            cpa16(sbase + (so + 2560 + b_st[j]) * 4, w1p + ko);
            cpa16(sbase + (so + 4736 + b_st[j]) * 4, w3p + ko);
        }
        cpa_commit();
    };

    float acc1[4][4][4] = {}, acc3[4][4][4] = {};

    issue(0); issue(1); issue(2);

    for (int kt = 0; kt < NK; ++kt) {
        if (kt + 2 < NK)      cpa_wait<2>();
        else if (kt + 1 < NK) cpa_wait<1>();
        else                  cpa_wait<0>();
        __syncthreads();                      // single barrier per chunk
        if (kt + NSTF - 1 < NK) issue(kt + NSTF - 1);

        const uint32_t* A0 = sm + (uint32_t)(kt & (NSTF - 1)) * SFW;
        const uint32_t* B1 = A0 + 2560;
        const uint32_t* B3 = A0 + 4736;

        uint32_t afr[2][4][4], bfr1[2][4][2], bfr3[2][4][2];
        #pragma unroll
        for (int ks = 0; ks < 2; ks++) {
            #pragma unroll
            for (int mi = 0; mi < 4; mi++) {
                const uint32_t* p = A0 + (uint32_t)(wm * 64 + mi * 16 + qg) * SA + ks * 8 + qt;
                afr[ks][mi][0] = c2t(p[0]);
                afr[ks][mi][1] = c2t(p[8 * SA]);
                afr[ks][mi][2] = c2t(p[4]);
                afr[ks][mi][3] = c2t(p[8 * SA + 4]);
            }
            #pragma unroll
            for (int ni = 0; ni < 4; ni++) {
                const uint32_t off = (uint32_t)(ks * 8 + qt) * SBW + wn * 32 + ni * 8 + qg;
                bfr1[ks][ni][0] = c2t(B1[off]);
                bfr1[ks][ni][1] = c2t(B1[off + 4 * SBW]);
                bfr3[ks][ni][0] = c2t(B3[off]);
                bfr3[ks][ni][1] = c2t(B3[off + 4 * SBW]);
            }
        }
        #pragma unroll
        for (int ks = 0; ks < 2; ks++)
            #pragma unroll
            for (int mi = 0; mi < 4; mi++)
                #pragma unroll
                for (int ni = 0; ni < 4; ni++) {
                    mma8(acc1[mi][ni], afr[ks][mi], bfr1[ks][ni]);
                    mma8(acc3[mi][ni], afr[ks][mi], bfr3[ks][ni]);
                }
    }

    // epilogue: SwiGLU -> g_H
    #pragma unroll
    for (int mi = 0; mi < 4; mi++) {
        #pragma unroll
        for (int half = 0; half < 2; half++) {
            const int row = m0 + wm * 64 + mi * 16 + qg + half * 8;
            if (row >= count) continue;
            #pragma unroll
            for (int ni = 0; ni < 4; ni++) {
                const int cn = n0 + wn * 32 + ni * 8 + 2 * qt;
                const float2 bb1 = *(const float2*)(b1 + (size_t)e * F_MID + cn);
                const float2 bb3 = *(const float2*)(b3 + (size_t)e * F_MID + cn);
                const float z10 = acc1[mi][ni][half * 2 + 0] + bb1.x;
                const float z11 = acc1[mi][ni][half * 2 + 1] + bb1.y;
                const float z30 = acc3[mi][ni][half * 2 + 0] + bb3.x;
                const float z31 = acc3[mi][ni][half * 2 + 1] + bb3.y;
                const float s0 = z10 / (1.0f + __expf(-z10));
                const float s1 = z11 / (1.0f + __expf(-z11));
                float2 v = { s0 * z30, s1 * z31 };
                *(float2*)(g_H + ((size_t)e * CAP + row) * F_MID + cn) = v;
            }
        }
    }
}

// ---------------------------------------------------------------- GEMM2
// out[tok] = g_H @ W2 + b2 (scatter). 3-stage cp.async, single barrier/chunk
// (issue(kt+2) writes stage (kt-1)%3, fenced by top barrier), exact tail
// waits, 56.8KB smem -> 2 CTA/SM. Grid: (n-tiles, m-tiles, e).
__global__ __launch_bounds__(256, 2) void gemm2_tc(
    const float* __restrict__ W, const float* __restrict__ bias,
    float* __restrict__ out)
{
    constexpr int NW = D_IN;
    constexpr int NK = F_MID / 16;   // 64

    const int e  = blockIdx.z;
    const int m0 = blockIdx.y * 128;
    const int n0 = blockIdx.x * 128;
    const int count = g_counts[e];
    if (m0 >= count) return;

    extern __shared__ uint32_t sm[];
    const uint32_t sbase = smem_u32(sm);

    const int tid = threadIdx.x, wid = tid >> 5, lane = tid & 31;
    const int wm = wid >> 2, wn = wid & 3;
    const int qg = lane >> 2, qt = lane & 3;

    const int ar  = tid >> 2;
    const int ak4 = (tid & 3) * 4;
    const float* ap[2];
    uint32_t a_st[2];
    #pragma unroll
    for (int j = 0; j < 2; j++) {
        const int grow = m0 + ar + 64 * j;
        ap[j]   = g_H + ((size_t)e * CAP + grow) * F_MID + ak4;
        a_st[j] = (uint32_t)(ar + 64 * j) * SA + ak4;
    }
    const int bkr = tid >> 5;
    const int bn4 = (tid & 31) * 4;
    const float* wp = W + ((size_t)e * F_MID + bkr) * NW + n0 + bn4;
    const uint32_t b_st[2] = { (uint32_t)bkr * SBW + bn4, (uint32_t)(bkr + 8) * SBW + bn4 };

    auto issue = [&](int kt) {
        const uint32_t so = (uint32_t)(kt % NST2) * S2W;
        #pragma unroll
        for (int j = 0; j < 2; j++)
            cpa16(sbase + (so + a_st[j]) * 4, ap[j] + kt * 16);
        #pragma unroll
        for (int j = 0; j < 2; j++)
            cpa16(sbase + (so + 2560 + b_st[j]) * 4, wp + ((size_t)kt * 16 + 8 * j) * NW);
        cpa_commit();
    };

    float acc[4][4][4] = {};

    issue(0); issue(1);

    for (int kt = 0; kt < NK; ++kt) {
        if (kt + 1 < NK) cpa_wait<1>();
        else             cpa_wait<0>();
        __syncthreads();                      // single barrier per chunk
        if (kt + 2 < NK) issue(kt + 2);

        const uint32_t* A0 = sm + (uint32_t)(kt % NST2) * S2W;
        const uint32_t* B0 = A0 + 2560;
        #pragma unroll
        for (int ks = 0; ks < 2; ks++) {
            uint32_t afr[4][4], bfr[4][2];
            #pragma unroll
            for (int mi = 0; mi < 4; mi++) {
                const uint32_t* p = A0 + (uint32_t)(wm * 64 + mi * 16 + qg) * SA + ks * 8 + qt;
                afr[mi][0] = c2t(p[0]);
                afr[mi][1] = c2t(p[8 * SA]);
                afr[mi][2] = c2t(p[4]);
                afr[mi][3] = c2t(p[8 * SA + 4]);
            }
            #pragma unroll
            for (int ni = 0; ni < 4; ni++) {
                const uint32_t off = (uint32_t)(ks * 8 + qt) * SBW + wn * 32 + ni * 8 + qg;
                bfr[ni][0] = c2t(B0[off]);
                bfr[ni][1] = c2t(B0[off + 4 * SBW]);
            }
            #pragma unroll
            for (int mi = 0; mi < 4; mi++)
                #pragma unroll
                for (int ni = 0; ni < 4; ni++)
                    mma8(acc[mi][ni], afr[mi], bfr[ni]);
        }
    }

    #pragma unroll
    for (int mi = 0; mi < 4; mi++) {
        #pragma unroll
        for (int half = 0; half < 2; half++) {
            const int row = m0 + wm * 64 + mi * 16 + qg + half * 8;
            if (row >= count) continue;
            const int tok = g_slots[e * CAP + row];
            #pragma unroll
            for (int ni = 0; ni < 4; ni++) {
                const int cn = n0 + wn * 32 + ni * 8 + 2 * qt;
                const float2 bb = *(const float2*)(bias + (size_t)e * NW + cn);
                float2 v = { acc[mi][ni][half * 2 + 0] + bb.x,
                             acc[mi][ni][half * 2 + 1] + bb.y };
                *(float2*)(out + (size_t)tok * D_IN + cn) = v;
            }
        }
    }
}

// ---------------------------------------------------------------- launch
extern "C" void kernel_launch(void* const* d_in, const int* in_sizes, int n_in,
                              void* d_out, int out_size) {
    const float* x   = (const float*)d_in[0];
    const float* W1  = (const float*)d_in[1];
    const float* b1  = (const float*)d_in[2];
    const float* W2  = (const float*)d_in[3];
    const float* b2  = (const float*)d_in[4];
    const float* W3  = (const float*)d_in[5];
    const float* b3  = (const float*)d_in[6];
    const int*   idx = (const int*)d_in[7];   // int32 on device (JAX x64 off)
    float* out = (float*)d_out;

    cudaFuncSetAttribute(gemm13_f, cudaFuncAttributeMaxDynamicSharedMemorySize, SMEMF);
    cudaFuncSetAttribute(gemm2_tc, cudaFuncAttributeMaxDynamicSharedMemorySize, SMEM2);

    build_slots<<<NEXP, 256>>>(idx);

    dim3 g13(F_MID / 128, CAP / 128, NEXP);   // (8, 4, 32) -- R13 order (best)
    gemm13_f<<<g13, 256, SMEMF>>>(x, W1, b1, W3, b3);

    dim3 g2(D_IN / 128, CAP / 128, NEXP);     // (16, 4, 32)
    gemm2_tc<<<g2, 256, SMEM2>>>(W2, b2, out);
}

// round 16
// speedup vs baseline: 1.6060x; 1.6060x over previous
#include <cuda_runtime.h>
#include <cstdint>

#define D_IN   2048
#define F_MID  1024
#define NEXP   32
#define CAP    512
#define TTOK   8192

#define SA   20u    // A smem row stride (words)
#define SBW  136u   // B smem row stride (words)
#define NSTF 4      // stages, fused kernel
#define NST2 2      // stages, gemm2 (<=48K smem -> 2 CTA/SM)

// per-stage words
#define SFW  (128u * SA + 2u * 16u * SBW)    // fused: 2560 + 4352 = 6912
#define S2W  (128u * SA + 16u * SBW)         // gemm2: 2560 + 2176 = 4736
#define SMEMF (NSTF * SFW * 4u)              // 110592 B
#define SMEM2 (NST2 * S2W * 4u)              // 37888 B

// scratch (__device__ globals: allocation-free rule)
__device__ int   g_slots[NEXP * CAP];
__device__ int   g_counts[NEXP];
__device__ float g_H[(size_t)NEXP * CAP * F_MID];  // 64 MB

__device__ __forceinline__ uint32_t smem_u32(const void* p) {
    uint32_t a;
    asm("{ .reg .u64 t; cvta.to.shared.u64 t, %1; cvt.u32.u64 %0, t; }" : "=r"(a) : "l"(p));
    return a;
}
__device__ __forceinline__ uint32_t f2tf(float f) {
    uint32_t u; asm("cvt.rna.tf32.f32 %0, %1;" : "=r"(u) : "f"(f)); return u;
}
__device__ __forceinline__ uint32_t c2t(uint32_t raw) {
    return f2tf(__uint_as_float(raw));
}
__device__ __forceinline__ void cpa16(uint32_t dst, const float* src) {
    asm volatile("cp.async.cg.shared.global [%0], [%1], 16;" :: "r"(dst), "l"(src) : "memory");
}
__device__ __forceinline__ void cpa_commit() {
    asm volatile("cp.async.commit_group;" ::: "memory");
}
template<int N> __device__ __forceinline__ void cpa_wait() {
    asm volatile("cp.async.wait_group %0;" :: "n"(N) : "memory");
}
__device__ __forceinline__ void mma8(float* c, const uint32_t* a, const uint32_t* b) {
    asm volatile(
        "mma.sync.aligned.m16n8k8.row.col.f32.tf32.tf32.f32 "
        "{%0,%1,%2,%3}, {%4,%5,%6,%7}, {%8,%9}, {%0,%1,%2,%3};"
        : "+f"(c[0]), "+f"(c[1]), "+f"(c[2]), "+f"(c[3])
        : "r"(a[0]), "r"(a[1]), "r"(a[2]), "r"(a[3]), "r"(b[0]), "r"(b[1]));
}

// ---------------------------------------------------------------- dispatch
__global__ void build_slots(const int* __restrict__ idx) {
    const int e = blockIdx.x, tid = threadIdx.x;
    const int lane = tid & 31, w = tid >> 5;
    __shared__ int wsum[8];
    int base = 0;
    for (int start = 0; start < TTOK; start += 256) {
        int t = start + tid;
        bool m = (idx[t] == e);
        unsigned bal = __ballot_sync(0xffffffffu, m);
        if (lane == 0) wsum[w] = __popc(bal);
        __syncthreads();
        int woff = 0, tot = 0;
        #pragma unroll
        for (int i = 0; i < 8; i++) { int v = wsum[i]; tot += v; if (i < w) woff += v; }
        if (m) {
            int pos = base + woff + __popc(bal & ((1u << lane) - 1u));
            if (pos < CAP) g_slots[e * CAP + pos] = t;
        }
        base += tot;
        __syncthreads();
    }
    if (tid == 0) g_counts[e] = base < CAP ? base : CAP;
}

// ---------------------------------------------------------------- fused GEMM1+3
// g_H = silu(gatherX @ W1 + b1) * (gatherX @ W3 + b3)
// CTA 128x128, K-chunk 16, 8 warps (2m x 4n), warp tile 64x32, dual acc.
// 4-stage cp.async, ONE barrier/chunk, exact tail waits,
// fragments double-buffered across the two ks steps.
__global__ __launch_bounds__(256, 1) void gemm13_f(
    const float* __restrict__ x,
    const float* __restrict__ W1, const float* __restrict__ b1,
    const float* __restrict__ W3, const float* __restrict__ b3)
{
    constexpr int NK = D_IN / 16;   // 128

    const int e  = blockIdx.z;
    const int m0 = blockIdx.y * 128;
    const int n0 = blockIdx.x * 128;
    const int count = g_counts[e];
    if (m0 >= count) return;

    extern __shared__ uint32_t sm[];
    const uint32_t sbase = smem_u32(sm);

    const int tid = threadIdx.x, wid = tid >> 5, lane = tid & 31;
    const int wm = wid >> 2, wn = wid & 3;
    const int qg = lane >> 2, qt = lane & 3;

    const int ar  = tid >> 2;
    const int ak4 = (tid & 3) * 4;
    const float* ap[2];
    uint32_t a_st[2];
    #pragma unroll
    for (int j = 0; j < 2; j++) {
        const int grow = m0 + ar + 64 * j;
        const int tok = (grow < count) ? g_slots[e * CAP + grow] : 0;
        ap[j]   = x + (size_t)tok * D_IN + ak4;
        a_st[j] = (uint32_t)(ar + 64 * j) * SA + ak4;
    }
    const int bkr = tid >> 5;
    const int bn4 = (tid & 31) * 4;
    const float* w1p = W1 + ((size_t)e * D_IN + bkr) * F_MID + n0 + bn4;
    const float* w3p = W3 + ((size_t)e * D_IN + bkr) * F_MID + n0 + bn4;
    const uint32_t b_st[2] = { (uint32_t)bkr * SBW + bn4, (uint32_t)(bkr + 8) * SBW + bn4 };

    auto issue = [&](int kt) {
        const uint32_t so = (uint32_t)(kt & (NSTF - 1)) * SFW;
        #pragma unroll
        for (int j = 0; j < 2; j++)
            cpa16(sbase + (so + a_st[j]) * 4, ap[j] + kt * 16);
        #pragma unroll
        for (int j = 0; j < 2; j++) {
            const size_t ko = ((size_t)kt * 16 + 8 * j) * F_MID;
            cpa16(sbase + (so + 2560 + b_st[j]) * 4, w1p + ko);
            cpa16(sbase + (so + 4736 + b_st[j]) * 4, w3p + ko);
        }
        cpa_commit();
    };

    float acc1[4][4][4] = {}, acc3[4][4][4] = {};

    issue(0); issue(1); issue(2);

    for (int kt = 0; kt < NK; ++kt) {
        if (kt + 2 < NK)      cpa_wait<2>();
        else if (kt + 1 < NK) cpa_wait<1>();
        else                  cpa_wait<0>();
        __syncthreads();                      // single barrier per chunk
        if (kt + NSTF - 1 < NK) issue(kt + NSTF - 1);

        const uint32_t* A0 = sm + (uint32_t)(kt & (NSTF - 1)) * SFW;
        const uint32_t* B1 = A0 + 2560;
        const uint32_t* B3 = A0 + 4736;

        uint32_t afr[2][4][4], bfr1[2][4][2], bfr3[2][4][2];
        #pragma unroll
        for (int ks = 0; ks < 2; ks++) {
            #pragma unroll
            for (int mi = 0; mi < 4; mi++) {
                const uint32_t* p = A0 + (uint32_t)(wm * 64 + mi * 16 + qg) * SA + ks * 8 + qt;
                afr[ks][mi][0] = c2t(p[0]);
                afr[ks][mi][1] = c2t(p[8 * SA]);
                afr[ks][mi][2] = c2t(p[4]);
                afr[ks][mi][3] = c2t(p[8 * SA + 4]);
            }
            #pragma unroll
            for (int ni = 0; ni < 4; ni++) {
                const uint32_t off = (uint32_t)(ks * 8 + qt) * SBW + wn * 32 + ni * 8 + qg;
                bfr1[ks][ni][0] = c2t(B1[off]);
                bfr1[ks][ni][1] = c2t(B1[off + 4 * SBW]);
                bfr3[ks][ni][0] = c2t(B3[off]);
                bfr3[ks][ni][1] = c2t(B3[off + 4 * SBW]);
            }
        }
        #pragma unroll
        for (int ks = 0; ks < 2; ks++)
            #pragma unroll
            for (int mi = 0; mi < 4; mi++)
                #pragma unroll
                for (int ni = 0; ni < 4; ni++) {
                    mma8(acc1[mi][ni], afr[ks][mi], bfr1[ks][ni]);
                    mma8(acc3[mi][ni], afr[ks][mi], bfr3[ks][ni]);
                }
    }

    // epilogue: SwiGLU -> g_H
    #pragma unroll
    for (int mi = 0; mi < 4; mi++) {
        #pragma unroll
        for (int half = 0; half < 2; half++) {
            const int row = m0 + wm * 64 + mi * 16 + qg + half * 8;
            if (row >= count) continue;
            #pragma unroll
            for (int ni = 0; ni < 4; ni++) {
                const int cn = n0 + wn * 32 + ni * 8 + 2 * qt;
                const float2 bb1 = *(const float2*)(b1 + (size_t)e * F_MID + cn);
                const float2 bb3 = *(const float2*)(b3 + (size_t)e * F_MID + cn);
                const float z10 = acc1[mi][ni][half * 2 + 0] + bb1.x;
                const float z11 = acc1[mi][ni][half * 2 + 1] + bb1.y;
                const float z30 = acc3[mi][ni][half * 2 + 0] + bb3.x;
                const float z31 = acc3[mi][ni][half * 2 + 1] + bb3.y;
                const float s0 = z10 / (1.0f + __expf(-z10));
                const float s1 = z11 / (1.0f + __expf(-z11));
                float2 v = { s0 * z30, s1 * z31 };
                *(float2*)(g_H + ((size_t)e * CAP + row) * F_MID + cn) = v;
            }
        }
    }
}

// ---------------------------------------------------------------- GEMM2
// out[tok] = g_H @ W2 + b2 (scatter). 2-stage cp.async, two barriers/chunk,
// exact tail waits, <=48K smem -> 2 CTA/SM.
__global__ __launch_bounds__(256, 2) void gemm2_tc(
    const float* __restrict__ W, const float* __restrict__ bias,
    float* __restrict__ out)
{
    constexpr int NW = D_IN;
    constexpr int NK = F_MID / 16;   // 64

    const int e  = blockIdx.z;
    const int m0 = blockIdx.y * 128;
    const int n0 = blockIdx.x * 128;
    const int count = g_counts[e];
    if (m0 >= count) return;

    extern __shared__ uint32_t sm[];
    const uint32_t sbase = smem_u32(sm);

    const int tid = threadIdx.x, wid = tid >> 5, lane = tid & 31;
    const int wm = wid >> 2, wn = wid & 3;
    const int qg = lane >> 2, qt = lane & 3;

    const int ar  = tid >> 2;
    const int ak4 = (tid & 3) * 4;
    const float* ap[2];
    uint32_t a_st[2];
    #pragma unroll
    for (int j = 0; j < 2; j++) {
        const int grow = m0 + ar + 64 * j;
        ap[j]   = g_H + ((size_t)e * CAP + grow) * F_MID + ak4;
        a_st[j] = (uint32_t)(ar + 64 * j) * SA + ak4;
    }
    const int bkr = tid >> 5;
    const int bn4 = (tid & 31) * 4;
    const float* wp = W + ((size_t)e * F_MID + bkr) * NW + n0 + bn4;
    const uint32_t b_st[2] = { (uint32_t)bkr * SBW + bn4, (uint32_t)(bkr + 8) * SBW + bn4 };

    auto issue = [&](int kt) {
        const uint32_t so = (uint32_t)(kt & (NST2 - 1)) * S2W;
        #pragma unroll
        for (int j = 0; j < 2; j++)
            cpa16(sbase + (so + a_st[j]) * 4, ap[j] + kt * 16);
        #pragma unroll
        for (int j = 0; j < 2; j++)
            cpa16(sbase + (so + 2560 + b_st[j]) * 4, wp + ((size_t)kt * 16 + 8 * j) * NW);
        cpa_commit();
    };

    float acc[4][4][4] = {};

    issue(0); issue(1);

    for (int kt = 0; kt < NK; ++kt) {
        if (kt + 1 < NK) cpa_wait<1>();
        else             cpa_wait<0>();
        __syncthreads();

        const uint32_t* A0 = sm + (uint32_t)(kt & (NST2 - 1)) * S2W;
        const uint32_t* B0 = A0 + 2560;
        #pragma unroll
        for (int ks = 0; ks < 2; ks++) {
            uint32_t afr[4][4], bfr[4][2];
            #pragma unroll
            for (int mi = 0; mi < 4; mi++) {
                const uint32_t* p = A0 + (uint32_t)(wm * 64 + mi * 16 + qg) * SA + ks * 8 + qt;
                afr[mi][0] = c2t(p[0]);
                afr[mi][1] = c2t(p[8 * SA]);
                afr[mi][2] = c2t(p[4]);
                afr[mi][3] = c2t(p[8 * SA + 4]);
            }
            #pragma unroll
            for (int ni = 0; ni < 4; ni++) {
                const uint32_t off = (uint32_t)(ks * 8 + qt) * SBW + wn * 32 + ni * 8 + qg;
                bfr[ni][0] = c2t(B0[off]);
                bfr[ni][1] = c2t(B0[off + 4 * SBW]);
            }
            #pragma unroll
            for (int mi = 0; mi < 4; mi++)
                #pragma unroll
                for (int ni = 0; ni < 4; ni++)
                    mma8(acc[mi][ni], afr[mi], bfr[ni]);
        }
        __syncthreads();
        if (kt + NST2 < NK) issue(kt + NST2);
    }

    #pragma unroll
    for (int mi = 0; mi < 4; mi++) {
        #pragma unroll
        for (int half = 0; half < 2; half++) {
            const int row = m0 + wm * 64 + mi * 16 + qg + half * 8;
            if (row >= count) continue;
            const int tok = g_slots[e * CAP + row];
            #pragma unroll
            for (int ni = 0; ni < 4; ni++) {
                const int cn = n0 + wn * 32 + ni * 8 + 2 * qt;
                const float2 bb = *(const float2*)(bias + (size_t)e * NW + cn);
                float2 v = { acc[mi][ni][half * 2 + 0] + bb.x,
                             acc[mi][ni][half * 2 + 1] + bb.y };
                *(float2*)(out + (size_t)tok * D_IN + cn) = v;
            }
        }
    }
}

// ---------------------------------------------------------------- launch
extern "C" void kernel_launch(void* const* d_in, const int* in_sizes, int n_in,
                              void* d_out, int out_size) {
    const float* x   = (const float*)d_in[0];
    const float* W1  = (const float*)d_in[1];
    const float* b1  = (const float*)d_in[2];
    const float* W2  = (const float*)d_in[3];
    const float* b2  = (const float*)d_in[4];
    const float* W3  = (const float*)d_in[5];
    const float* b3  = (const float*)d_in[6];
    const int*   idx = (const int*)d_in[7];   // int32 on device (JAX x64 off)
    float* out = (float*)d_out;

    cudaFuncSetAttribute(gemm13_f, cudaFuncAttributeMaxDynamicSharedMemorySize, SMEMF);
    cudaFuncSetAttribute(gemm2_tc, cudaFuncAttributeMaxDynamicSharedMemorySize, SMEM2);

    build_slots<<<NEXP, 256>>>(idx);

    dim3 g13(F_MID / 128, CAP / 128, NEXP);   // (8, 4, 32)
    gemm13_f<<<g13, 256, SMEMF>>>(x, W1, b1, W3, b3);

    dim3 g2(D_IN / 128, CAP / 128, NEXP);     // (16, 4, 32)
    gemm2_tc<<<g2, 256, SMEM2>>>(W2, b2, out);
}